// round 1
// baseline (speedup 1.0000x reference)
#include <cuda_runtime.h>
#include <math.h>

#define DIM   512
#define NS    8
#define BATCH 128
#define NTOK  1024
#define HIDN  512
#define NROWS (BATCH*NTOK)   /* 131072 */
#define SROWS (BATCH*NS)     /* 1024   */
#define ATT_SCALE 0.04419417382415922f  /* 512^-0.5 */
#define LN_EPS 1e-5f
#define ATT_EPS 1e-8f

/* ---------------- scratch (device globals; no allocation) ---------------- */
__device__ float g_xn[(size_t)NROWS*DIM];
__device__ float g_k [(size_t)NROWS*DIM];
__device__ float g_v [(size_t)NROWS*DIM];
__device__ float g_s [SROWS*DIM];
__device__ float g_q [SROWS*DIM];
__device__ float g_attn[SROWS*NTOK];
__device__ float g_rowsum[SROWS];
__device__ float g_upd[SROWS*DIM];
__device__ float g_xg[SROWS*3*DIM];
__device__ float g_hg[SROWS*3*DIM];
__device__ float g_hid[SROWS*HIDN];

/* ---------------- slot init: mu + exp(logsigma)*noise ---------------- */
__global__ void init_slots(const float* __restrict__ noise,
                           const float* __restrict__ mu,
                           const float* __restrict__ logsigma,
                           float* __restrict__ slots) {
    int idx = blockIdx.x * blockDim.x + threadIdx.x;   /* 524288 */
    int d = idx & (DIM - 1);
    slots[idx] = mu[d] + expf(logsigma[d]) * noise[idx];
}

/* ---------------- row LayerNorm (cols = 512), 128 threads/row ---------------- */
__global__ void ln_rows(const float* __restrict__ in, float* __restrict__ out,
                        const float* __restrict__ gamma, const float* __restrict__ beta) {
    int row = blockIdx.x;
    int t = threadIdx.x;                       /* 128 threads, one float4 each */
    const float4* ip = (const float4*)(in + (size_t)row * DIM);
    float4 x = ip[t];
    float s  = x.x + x.y + x.z + x.w;
    float ss = x.x*x.x + x.y*x.y + x.z*x.z + x.w*x.w;
    #pragma unroll
    for (int o = 16; o > 0; o >>= 1) {
        s  += __shfl_down_sync(0xffffffffu, s,  o);
        ss += __shfl_down_sync(0xffffffffu, ss, o);
    }
    __shared__ float sh[8];
    int w = t >> 5, l = t & 31;
    if (l == 0) { sh[w] = s; sh[4 + w] = ss; }
    __syncthreads();
    s  = sh[0] + sh[1] + sh[2] + sh[3];
    ss = sh[4] + sh[5] + sh[6] + sh[7];
    float mean = s * (1.0f / DIM);
    float var  = ss * (1.0f / DIM) - mean * mean;
    float rstd = rsqrtf(var + LN_EPS);
    float4 g = ((const float4*)gamma)[t];
    float4 b = ((const float4*)beta)[t];
    float4 o4;
    o4.x = (x.x - mean) * rstd * g.x + b.x;
    o4.y = (x.y - mean) * rstd * g.y + b.y;
    o4.z = (x.z - mean) * rstd * g.z + b.z;
    o4.w = (x.w - mean) * rstd * g.w + b.w;
    ((float4*)(out + (size_t)row * DIM))[t] = o4;
}

/* ---------------- SGEMM: C[m,n] = sum_k A[m,k]*W[n,k] + bias[n] ----------------
   BM=BN=128, BK=16, 256 threads, 8x8 per thread. All dims multiples of tile. */
template<int RELU, int ADDC>
__global__ __launch_bounds__(256) void sgemm(const float* __restrict__ A,
                                             const float* __restrict__ W,
                                             const float* __restrict__ bias,
                                             float* __restrict__ C,
                                             int M, int N, int K) {
    __shared__ float As[16][132];
    __shared__ float Ws[16][132];
    int tid = threadIdx.x;
    int tx = tid & 15, ty = tid >> 4;
    int m0 = blockIdx.y * 128, n0 = blockIdx.x * 128;
    int lr = tid >> 2;
    int lc = (tid & 3) * 4;
    const float* Ab = A + (size_t)m0 * K;
    const float* Wb = W + (size_t)n0 * K;
    float acc[8][8];
    #pragma unroll
    for (int i = 0; i < 8; i++)
        #pragma unroll
        for (int j = 0; j < 8; j++) acc[i][j] = 0.f;

    for (int k0 = 0; k0 < K; k0 += 16) {
        float4 a0 = *(const float4*)(Ab + (size_t)lr        * K + k0 + lc);
        float4 a1 = *(const float4*)(Ab + (size_t)(lr + 64) * K + k0 + lc);
        float4 w0 = *(const float4*)(Wb + (size_t)lr        * K + k0 + lc);
        float4 w1 = *(const float4*)(Wb + (size_t)(lr + 64) * K + k0 + lc);
        __syncthreads();
        As[lc+0][lr] = a0.x; As[lc+1][lr] = a0.y; As[lc+2][lr] = a0.z; As[lc+3][lr] = a0.w;
        As[lc+0][lr+64] = a1.x; As[lc+1][lr+64] = a1.y; As[lc+2][lr+64] = a1.z; As[lc+3][lr+64] = a1.w;
        Ws[lc+0][lr] = w0.x; Ws[lc+1][lr] = w0.y; Ws[lc+2][lr] = w0.z; Ws[lc+3][lr] = w0.w;
        Ws[lc+0][lr+64] = w1.x; Ws[lc+1][lr+64] = w1.y; Ws[lc+2][lr+64] = w1.z; Ws[lc+3][lr+64] = w1.w;
        __syncthreads();
        #pragma unroll
        for (int kk = 0; kk < 16; kk++) {
            float av[8], wv[8];
            #pragma unroll
            for (int i = 0; i < 8; i++) av[i] = As[kk][ty*8 + i];
            #pragma unroll
            for (int j = 0; j < 8; j++) wv[j] = Ws[kk][tx*8 + j];
            #pragma unroll
            for (int i = 0; i < 8; i++)
                #pragma unroll
                for (int j = 0; j < 8; j++) acc[i][j] += av[i] * wv[j];
        }
    }
    #pragma unroll
    for (int i = 0; i < 8; i++) {
        size_t crow = (size_t)(m0 + ty*8 + i) * N;
        #pragma unroll
        for (int j = 0; j < 8; j++) {
            int n = n0 + tx*8 + j;
            float cv = acc[i][j] + bias[n];
            if (RELU) cv = fmaxf(cv, 0.f);
            if (ADDC) cv += C[crow + n];
            C[crow + n] = cv;
        }
    }
}

/* ---------------- zero rowsum ---------------- */
__global__ void zero_rowsum(float* __restrict__ rs) {
    rs[blockIdx.x * blockDim.x + threadIdx.x] = 0.f;
}

/* ---- dots + competitive softmax. grid (NTOK/128, BATCH), 128 threads.
   1 thread = 1 token column j: 8 slot dots in regs; softmax over slots is local. */
__global__ __launch_bounds__(128) void dots_softmax(const float* __restrict__ kmat,
                                                    const float* __restrict__ qmat,
                                                    float* __restrict__ attn,
                                                    float* __restrict__ rowsum) {
    int b = blockIdx.y;
    int j = blockIdx.x * 128 + threadIdx.x;
    __shared__ float4 qs[NS][DIM/4];           /* 16 KB, broadcast reads */
    const float4* qsrc = (const float4*)(qmat + (size_t)b * NS * DIM);
    for (int idx = threadIdx.x; idx < NS * DIM / 4; idx += 128)
        qs[idx >> 7][idx & 127] = qsrc[idx];
    __syncthreads();

    float acc[NS];
    #pragma unroll
    for (int i = 0; i < NS; i++) acc[i] = 0.f;
    const float4* kp = (const float4*)(kmat + (size_t)(b * NTOK + j) * DIM);
    #pragma unroll 4
    for (int d4 = 0; d4 < DIM/4; d4++) {
        float4 kv = kp[d4];
        #pragma unroll
        for (int i = 0; i < NS; i++) {
            float4 qv = qs[i][d4];
            acc[i] += kv.x*qv.x + kv.y*qv.y + kv.z*qv.z + kv.w*qv.w;
        }
    }
    float m = -1e30f;
    #pragma unroll
    for (int i = 0; i < NS; i++) { acc[i] *= ATT_SCALE; m = fmaxf(m, acc[i]); }
    float sum = 0.f;
    #pragma unroll
    for (int i = 0; i < NS; i++) { acc[i] = expf(acc[i] - m); sum += acc[i]; }
    float inv = 1.0f / sum;
    #pragma unroll
    for (int i = 0; i < NS; i++) {
        float p = acc[i] * inv + ATT_EPS;
        acc[i] = p;
        attn[(size_t)(b * NS + i) * NTOK + j] = p;
    }
    /* reduce over j for normalization denominator */
    #pragma unroll
    for (int i = 0; i < NS; i++) {
        float s = acc[i];
        #pragma unroll
        for (int o = 16; o > 0; o >>= 1) s += __shfl_down_sync(0xffffffffu, s, o);
        if ((threadIdx.x & 31) == 0) atomicAdd(&rowsum[b * NS + i], s);
    }
}

/* ---- updates[b,i,d] = sum_j v[b,j,d]*attn[b,i,j]/rowsum[b,i].
   grid BATCH, 256 threads, 2 d per thread (coalesced V along d). ---- */
__global__ __launch_bounds__(256) void attn_apply(const float* __restrict__ vmat,
                                                  const float* __restrict__ attn,
                                                  const float* __restrict__ rowsum,
                                                  float* __restrict__ upd) {
    int b = blockIdx.x;
    int t = threadIdx.x;
    int d = t * 2;
    __shared__ float as[NS][256];
    float accx[NS], accy[NS];
    #pragma unroll
    for (int i = 0; i < NS; i++) { accx[i] = 0.f; accy[i] = 0.f; }
    for (int j0 = 0; j0 < NTOK; j0 += 256) {
        __syncthreads();
        #pragma unroll
        for (int i = 0; i < NS; i++)
            as[i][t] = attn[(size_t)(b * NS + i) * NTOK + j0 + t];
        __syncthreads();
        #pragma unroll 4
        for (int jj = 0; jj < 256; jj++) {
            float2 vv = *(const float2*)(vmat + (size_t)(b * NTOK + j0 + jj) * DIM + d);
            #pragma unroll
            for (int i = 0; i < NS; i++) {
                float a = as[i][jj];
                accx[i] += vv.x * a;
                accy[i] += vv.y * a;
            }
        }
    }
    #pragma unroll
    for (int i = 0; i < NS; i++) {
        float inv = 1.0f / rowsum[b * NS + i];
        float* o = upd + (size_t)(b * NS + i) * DIM + d;
        o[0] = accx[i] * inv;
        o[1] = accy[i] * inv;
    }
}

/* ---------------- GRU gate: slots = (1-z)*n + z*prev ---------------- */
__global__ void gru_gate(const float* __restrict__ xg, const float* __restrict__ hg,
                         float* __restrict__ slots) {
    int row = blockIdx.x;
    int c = threadIdx.x;                       /* 512 */
    size_t base = (size_t)row * 3 * DIM;
    float xr = xg[base + c],        hr = hg[base + c];
    float xz = xg[base + DIM + c],  hz = hg[base + DIM + c];
    float xn = xg[base + 2*DIM + c], hn = hg[base + 2*DIM + c];
    float r = 1.0f / (1.0f + expf(-(xr + hr)));
    float z = 1.0f / (1.0f + expf(-(xz + hz)));
    float n = tanhf(xn + r * hn);
    size_t si = (size_t)row * DIM + c;
    float prev = slots[si];
    slots[si] = (1.0f - z) * n + z * prev;
}

/* ---------------- host ---------------- */
static float* sym(const void* s) {
    void* p = nullptr;
    cudaGetSymbolAddress(&p, s);
    return (float*)p;
}

extern "C" void kernel_launch(void* const* d_in, const int* in_sizes, int n_in,
                              void* d_out, int out_size) {
    const float* inputs    = (const float*)d_in[0];
    const float* noise     = (const float*)d_in[1];
    const float* mu        = (const float*)d_in[2];
    const float* logsigma  = (const float*)d_in[3];
    const float* g_in      = (const float*)d_in[4];
    const float* be_in     = (const float*)d_in[5];
    const float* g_sl      = (const float*)d_in[6];
    const float* be_sl     = (const float*)d_in[7];
    const float* g_ff      = (const float*)d_in[8];
    const float* be_ff     = (const float*)d_in[9];
    const float* Wq        = (const float*)d_in[10];
    const float* bq        = (const float*)d_in[11];
    const float* Wk        = (const float*)d_in[12];
    const float* bk        = (const float*)d_in[13];
    const float* Wv        = (const float*)d_in[14];
    const float* bv        = (const float*)d_in[15];
    const float* W_ih      = (const float*)d_in[16];
    const float* b_ih      = (const float*)d_in[17];
    const float* W_hh      = (const float*)d_in[18];
    const float* b_hh      = (const float*)d_in[19];
    const float* W1        = (const float*)d_in[20];
    const float* b1        = (const float*)d_in[21];
    const float* W2        = (const float*)d_in[22];
    const float* b2        = (const float*)d_in[23];
    float* slots = (float*)d_out;

    float* xn   = sym(g_xn);
    float* kbuf = sym(g_k);
    float* vbuf = sym(g_v);
    float* sbuf = sym(g_s);
    float* qbuf = sym(g_q);
    float* attn = sym(g_attn);
    float* rsum = sym(g_rowsum);
    float* upd  = sym(g_upd);
    float* xg   = sym(g_xg);
    float* hg   = sym(g_hg);
    float* hid  = sym(g_hid);

    /* slot init */
    init_slots<<<SROWS*DIM/256, 256>>>(noise, mu, logsigma, slots);
    /* x = LN(inputs); K,V projections */
    ln_rows<<<NROWS, 128>>>(inputs, xn, g_in, be_in);
    sgemm<0,0><<<dim3(DIM/128, NROWS/128), 256>>>(xn, Wk, bk, kbuf, NROWS, DIM, DIM);
    sgemm<0,0><<<dim3(DIM/128, NROWS/128), 256>>>(xn, Wv, bv, vbuf, NROWS, DIM, DIM);

    for (int it = 0; it < 3; it++) {
        ln_rows<<<SROWS, 128>>>(slots, sbuf, g_sl, be_sl);
        sgemm<0,0><<<dim3(DIM/128, SROWS/128), 256>>>(sbuf, Wq, bq, qbuf, SROWS, DIM, DIM);
        zero_rowsum<<<SROWS/256, 256>>>(rsum);
        dots_softmax<<<dim3(NTOK/128, BATCH), 128>>>(kbuf, qbuf, attn, rsum);
        attn_apply<<<BATCH, 256>>>(vbuf, attn, rsum, upd);
        sgemm<0,0><<<dim3(3*DIM/128, SROWS/128), 256>>>(upd,   W_ih, b_ih, xg, SROWS, 3*DIM, DIM);
        sgemm<0,0><<<dim3(3*DIM/128, SROWS/128), 256>>>(slots, W_hh, b_hh, hg, SROWS, 3*DIM, DIM);
        gru_gate<<<SROWS, DIM>>>(xg, hg, slots);
        ln_rows<<<SROWS, 128>>>(slots, sbuf, g_ff, be_ff);
        sgemm<1,0><<<dim3(HIDN/128, SROWS/128), 256>>>(sbuf, W1, b1, hid, SROWS, HIDN, DIM);
        sgemm<0,1><<<dim3(DIM/128, SROWS/128), 256>>>(hid, W2, b2, slots, SROWS, DIM, HIDN);
    }
    (void)in_sizes; (void)n_in; (void)out_size;
}

// round 3
// speedup vs baseline: 2.2874x; 2.2874x over previous
#include <cuda_runtime.h>
#include <math.h>
#include <stdint.h>

#define DIM   512
#define NS    8
#define BATCH 128
#define NTOK  1024
#define HIDN  512
#define NROWS (BATCH*NTOK)   /* 131072 */
#define SROWS (BATCH*NS)     /* 1024   */
#define ATT_SCALE 0.04419417382415922f
#define LN_EPS 1e-5f
#define ATT_EPS 1e-8f

/* ---------------- scratch (device globals; no allocation) ---------------- */
__device__ float g_xn[(size_t)NROWS*DIM];
__device__ float g_kv[(size_t)NROWS*1024];      /* k = cols 0..511, v = cols 512..1023 */
__device__ float g_wkv[1024*DIM];
__device__ float g_bkv[1024];
__device__ float g_Wq_r[DIM*DIM];
__device__ float g_Wih_r[3*DIM*DIM];
__device__ float g_Whh_r[3*DIM*DIM];
__device__ float g_W1_r[HIDN*DIM];
__device__ float g_W2_r[DIM*HIDN];
__device__ float g_s [SROWS*DIM];
__device__ float g_sr[SROWS*DIM];
__device__ float g_q [SROWS*DIM];
__device__ float g_attn[SROWS*NTOK];
__device__ float g_rowsum[SROWS];
__device__ float g_upd[SROWS*DIM];
__device__ float g_xg[SROWS*3*DIM];
__device__ float g_hg[SROWS*3*DIM];
__device__ float g_hid[SROWS*HIDN];

/* ---------------- helpers ---------------- */
__device__ __forceinline__ float rtf32(float x) {
    uint32_t u; asm("cvt.rna.tf32.f32 %0, %1;" : "=r"(u) : "f"(x));
    return __uint_as_float(u);
}
__device__ __forceinline__ uint32_t s2u(const void* p) {
    uint32_t a;
    asm("{ .reg .u64 t; cvta.to.shared.u64 t, %1; cvt.u32.u64 %0, t; }" : "=r"(a) : "l"(p));
    return a;
}

#define CP16(dst, src) \
    asm volatile("cp.async.cg.shared.global [%0], [%1], 16;" :: "r"(dst), "l"(src))
#define CP_COMMIT() asm volatile("cp.async.commit_group;" ::: "memory")
#define CP_WAIT(n)  asm volatile("cp.async.wait_group %0;" :: "n"(n) : "memory")

#define MMA_TF32(d, a, b) \
    asm volatile("mma.sync.aligned.m16n8k8.row.col.f32.tf32.tf32.f32 " \
        "{%0,%1,%2,%3}, {%4,%5,%6,%7}, {%8,%9}, {%0,%1,%2,%3};" \
        : "+f"((d)[0]), "+f"((d)[1]), "+f"((d)[2]), "+f"((d)[3]) \
        : "r"(__float_as_uint((a)[0])), "r"(__float_as_uint((a)[1])), \
          "r"(__float_as_uint((a)[2])), "r"(__float_as_uint((a)[3])), \
          "r"(__float_as_uint((b)[0])), "r"(__float_as_uint((b)[1])))

/* ============ tf32 mma.sync GEMM: C[m,n] = A[m,:]·W[n,:] + bias[n] ============
   BM=BN=128, BK=32, 256 threads (8 warps, warp grid 2m x 4n, warp tile 64x32),
   double-buffered cp.async. Requires M,N mult 128, K mult 32. Operands
   pre-rounded to tf32 (rna) by producers. Smem row stride 36 -> fragment LDS
   bank = (4m+k) mod 32, conflict-free. */
#define ASTR 36
#define STG_FLOATS (2 * 128 * ASTR)          /* A tile + B tile per stage */
#define GSMEM (2 * STG_FLOATS * 4)           /* 73728 bytes */

template<int RELU, int ADDC, int RND>
__global__ __launch_bounds__(256) void mma_gemm(const float* __restrict__ A,
                                                const float* __restrict__ W,
                                                const float* __restrict__ bias,
                                                float* __restrict__ C,
                                                int M, int N, int K) {
    extern __shared__ float smem[];
    int tid = threadIdx.x;
    int lane = tid & 31, wid = tid >> 5;
    int wm = wid & 1, wn = wid >> 1;
    int m0 = blockIdx.y * 128, n0 = blockIdx.x * 128;
    int r0 = lane >> 2, k4 = lane & 3;

    float acc[4][4][4];
    #pragma unroll
    for (int mt = 0; mt < 4; mt++)
        #pragma unroll
        for (int nt = 0; nt < 4; nt++)
            #pragma unroll
            for (int i = 0; i < 4; i++) acc[mt][nt][i] = 0.f;

    const int KT = K >> 5;

    /* stage loader */
    int lrow = tid >> 3;              /* 0..31? no: 256 threads, idx below */
    (void)lrow;
    auto load_stage = [&](int kt, int s) {
        const float* Ag = A + (size_t)m0 * K + (kt << 5);
        const float* Wg = W + (size_t)n0 * K + (kt << 5);
        float* Ab = smem + s * STG_FLOATS;
        float* Bb = Ab + 128 * ASTR;
        #pragma unroll
        for (int i = 0; i < 4; i++) {
            int idx = tid + (i << 8);
            int r = idx >> 3, c4 = (idx & 7) << 2;
            CP16(s2u(Ab + r * ASTR + c4), Ag + (size_t)r * K + c4);
            CP16(s2u(Bb + r * ASTR + c4), Wg + (size_t)r * K + c4);
        }
    };

    load_stage(0, 0); CP_COMMIT();

    for (int kt = 0; kt < KT; kt++) {
        int s = kt & 1;
        if (kt + 1 < KT) { load_stage(kt + 1, s ^ 1); CP_COMMIT(); CP_WAIT(1); }
        else             { CP_WAIT(0); }
        __syncthreads();

        const float* Ab = smem + s * STG_FLOATS + (wm * 64 + r0) * ASTR + k4;
        const float* Bb = smem + s * STG_FLOATS + 128 * ASTR + (wn * 32 + r0) * ASTR + k4;
        #pragma unroll
        for (int ks = 0; ks < 4; ks++) {
            int kb = ks << 3;
            float af[4][4], bf[4][2];
            #pragma unroll
            for (int mt = 0; mt < 4; mt++) {
                af[mt][0] = Ab[(mt * 16    ) * ASTR + kb];
                af[mt][1] = Ab[(mt * 16 + 8) * ASTR + kb];
                af[mt][2] = Ab[(mt * 16    ) * ASTR + kb + 4];
                af[mt][3] = Ab[(mt * 16 + 8) * ASTR + kb + 4];
            }
            #pragma unroll
            for (int nt = 0; nt < 4; nt++) {
                bf[nt][0] = Bb[nt * 8 * ASTR + kb];
                bf[nt][1] = Bb[nt * 8 * ASTR + kb + 4];
            }
            #pragma unroll
            for (int mt = 0; mt < 4; mt++)
                #pragma unroll
                for (int nt = 0; nt < 4; nt++)
                    MMA_TF32(acc[mt][nt], af[mt], bf[nt]);
        }
        __syncthreads();
    }

    /* epilogue */
    #pragma unroll
    for (int mt = 0; mt < 4; mt++) {
        int mg = m0 + wm * 64 + mt * 16 + r0;
        #pragma unroll
        for (int nt = 0; nt < 4; nt++) {
            int ng = n0 + wn * 32 + nt * 8 + (k4 << 1);
            float b0 = bias[ng], b1 = bias[ng + 1];
            float* c0p = C + (size_t)mg * N + ng;
            float* c1p = C + (size_t)(mg + 8) * N + ng;
            float o0 = acc[mt][nt][0] + b0, o1 = acc[mt][nt][1] + b1;
            float o2 = acc[mt][nt][2] + b0, o3 = acc[mt][nt][3] + b1;
            if (RELU) {
                o0 = fmaxf(o0, 0.f); o1 = fmaxf(o1, 0.f);
                o2 = fmaxf(o2, 0.f); o3 = fmaxf(o3, 0.f);
            }
            if (ADDC) {
                float2 e0 = *(const float2*)c0p;
                float2 e1 = *(const float2*)c1p;
                o0 += e0.x; o1 += e0.y; o2 += e1.x; o3 += e1.y;
            }
            if (RND) { o0 = rtf32(o0); o1 = rtf32(o1); o2 = rtf32(o2); o3 = rtf32(o3); }
            *(float2*)c0p = make_float2(o0, o1);
            *(float2*)c1p = make_float2(o2, o3);
        }
    }
}

/* ---------------- slot init ---------------- */
__global__ void init_slots(const float* __restrict__ noise,
                           const float* __restrict__ mu,
                           const float* __restrict__ logsigma,
                           float* __restrict__ slots) {
    int idx = blockIdx.x * blockDim.x + threadIdx.x;
    int d = idx & (DIM - 1);
    slots[idx] = mu[d] + expf(logsigma[d]) * noise[idx];
}

/* ---------------- pack+round [Wk;Wv] and biases ---------------- */
__global__ void pack_kv(const float* __restrict__ Wk, const float* __restrict__ bk,
                        const float* __restrict__ Wv, const float* __restrict__ bv,
                        float* __restrict__ Wkv, float* __restrict__ bkv) {
    int i = blockIdx.x * 256 + threadIdx.x;  /* 524288 */
    float w = (i < DIM * DIM) ? Wk[i] : Wv[i - DIM * DIM];
    Wkv[i] = rtf32(w);
    if (i < 1024) bkv[i] = (i < 512) ? bk[i] : bv[i - 512];
}

/* ---------------- round-copy to tf32 ---------------- */
__global__ void round_copy(const float* __restrict__ src, float* __restrict__ dst, int n) {
    int i = blockIdx.x * 256 + threadIdx.x;
    if (i < n) dst[i] = rtf32(src[i]);
}

/* ---------------- row LayerNorm (cols = 512), output rounded to tf32 ------- */
__global__ void ln_rows(const float* __restrict__ in, float* __restrict__ out,
                        const float* __restrict__ gamma, const float* __restrict__ beta) {
    int row = blockIdx.x;
    int t = threadIdx.x;
    const float4* ip = (const float4*)(in + (size_t)row * DIM);
    float4 x = ip[t];
    float s  = x.x + x.y + x.z + x.w;
    float ss = x.x*x.x + x.y*x.y + x.z*x.z + x.w*x.w;
    #pragma unroll
    for (int o = 16; o > 0; o >>= 1) {
        s  += __shfl_down_sync(0xffffffffu, s,  o);
        ss += __shfl_down_sync(0xffffffffu, ss, o);
    }
    __shared__ float sh[8];
    int w = t >> 5, l = t & 31;
    if (l == 0) { sh[w] = s; sh[4 + w] = ss; }
    __syncthreads();
    s  = sh[0] + sh[1] + sh[2] + sh[3];
    ss = sh[4] + sh[5] + sh[6] + sh[7];
    float mean = s * (1.0f / DIM);
    float var  = ss * (1.0f / DIM) - mean * mean;
    float rstd = rsqrtf(var + LN_EPS);
    float4 g = ((const float4*)gamma)[t];
    float4 b = ((const float4*)beta)[t];
    float4 o4;
    o4.x = rtf32((x.x - mean) * rstd * g.x + b.x);
    o4.y = rtf32((x.y - mean) * rstd * g.y + b.y);
    o4.z = rtf32((x.z - mean) * rstd * g.z + b.z);
    o4.w = rtf32((x.w - mean) * rstd * g.w + b.w);
    ((float4*)(out + (size_t)row * DIM))[t] = o4;
}

/* ---------------- zero rowsum ---------------- */
__global__ void zero_rowsum(float* __restrict__ rs) {
    rs[blockIdx.x * blockDim.x + threadIdx.x] = 0.f;
}

/* ---- dots + competitive softmax over slots; kv stride 1024, k at offset 0 ---- */
__global__ __launch_bounds__(128) void dots_softmax(const float* __restrict__ kv,
                                                    const float* __restrict__ qmat,
                                                    float* __restrict__ attn,
                                                    float* __restrict__ rowsum) {
    int b = blockIdx.y;
    int j = blockIdx.x * 128 + threadIdx.x;
    __shared__ float4 qs[NS][DIM/4];
    const float4* qsrc = (const float4*)(qmat + (size_t)b * NS * DIM);
    for (int idx = threadIdx.x; idx < NS * DIM / 4; idx += 128)
        qs[idx >> 7][idx & 127] = qsrc[idx];
    __syncthreads();

    float acc[NS];
    #pragma unroll
    for (int i = 0; i < NS; i++) acc[i] = 0.f;
    const float4* kp = (const float4*)(kv + (size_t)(b * NTOK + j) * 1024);
    #pragma unroll 4
    for (int d4 = 0; d4 < DIM/4; d4++) {
        float4 k4 = kp[d4];
        #pragma unroll
        for (int i = 0; i < NS; i++) {
            float4 qv = qs[i][d4];
            acc[i] += k4.x*qv.x + k4.y*qv.y + k4.z*qv.z + k4.w*qv.w;
        }
    }
    float m = -1e30f;
    #pragma unroll
    for (int i = 0; i < NS; i++) { acc[i] *= ATT_SCALE; m = fmaxf(m, acc[i]); }
    float sum = 0.f;
    #pragma unroll
    for (int i = 0; i < NS; i++) { acc[i] = expf(acc[i] - m); sum += acc[i]; }
    float inv = 1.0f / sum;
    #pragma unroll
    for (int i = 0; i < NS; i++) {
        float p = acc[i] * inv + ATT_EPS;
        acc[i] = p;
        attn[(size_t)(b * NS + i) * NTOK + j] = p;
    }
    #pragma unroll
    for (int i = 0; i < NS; i++) {
        float s = acc[i];
        #pragma unroll
        for (int o = 16; o > 0; o >>= 1) s += __shfl_down_sync(0xffffffffu, s, o);
        if ((threadIdx.x & 31) == 0) atomicAdd(&rowsum[b * NS + i], s);
    }
}

/* ---- updates: v at kv offset 512, stride 1024; output rounded to tf32 ---- */
__global__ __launch_bounds__(256) void attn_apply(const float* __restrict__ kv,
                                                  const float* __restrict__ attn,
                                                  const float* __restrict__ rowsum,
                                                  float* __restrict__ upd) {
    int b = blockIdx.x;
    int t = threadIdx.x;
    int d = t * 2;
    __shared__ float as[NS][256];
    float accx[NS], accy[NS];
    #pragma unroll
    for (int i = 0; i < NS; i++) { accx[i] = 0.f; accy[i] = 0.f; }
    for (int j0 = 0; j0 < NTOK; j0 += 256) {
        __syncthreads();
        #pragma unroll
        for (int i = 0; i < NS; i++)
            as[i][t] = attn[(size_t)(b * NS + i) * NTOK + j0 + t];
        __syncthreads();
        #pragma unroll 4
        for (int jj = 0; jj < 256; jj++) {
            float2 vv = *(const float2*)(kv + (size_t)(b * NTOK + j0 + jj) * 1024 + 512 + d);
            #pragma unroll
            for (int i = 0; i < NS; i++) {
                float a = as[i][jj];
                accx[i] += vv.x * a;
                accy[i] += vv.y * a;
            }
        }
    }
    #pragma unroll
    for (int i = 0; i < NS; i++) {
        float inv = 1.0f / rowsum[b * NS + i];
        float* o = upd + (size_t)(b * NS + i) * DIM + d;
        o[0] = rtf32(accx[i] * inv);
        o[1] = rtf32(accy[i] * inv);
    }
}

/* ---------------- GRU gate ---------------- */
__global__ void gru_gate(const float* __restrict__ xg, const float* __restrict__ hg,
                         float* __restrict__ slots) {
    int row = blockIdx.x;
    int c = threadIdx.x;
    size_t base = (size_t)row * 3 * DIM;
    float xr = xg[base + c],         hr = hg[base + c];
    float xz = xg[base + DIM + c],   hz = hg[base + DIM + c];
    float xn = xg[base + 2*DIM + c], hn = hg[base + 2*DIM + c];
    float r = 1.0f / (1.0f + expf(-(xr + hr)));
    float z = 1.0f / (1.0f + expf(-(xz + hz)));
    float n = tanhf(xn + r * hn);
    size_t si = (size_t)row * DIM + c;
    float prev = slots[si];
    slots[si] = (1.0f - z) * n + z * prev;
}

/* ---------------- host ---------------- */
static float* sym(const void* s) {
    void* p = nullptr;
    cudaGetSymbolAddress(&p, s);
    return (float*)p;
}

extern "C" void kernel_launch(void* const* d_in, const int* in_sizes, int n_in,
                              void* d_out, int out_size) {
    const float* inputs    = (const float*)d_in[0];
    const float* noise     = (const float*)d_in[1];
    const float* mu        = (const float*)d_in[2];
    const float* logsigma  = (const float*)d_in[3];
    const float* gi        = (const float*)d_in[4];
    const float* bei       = (const float*)d_in[5];
    const float* gsl       = (const float*)d_in[6];
    const float* besl      = (const float*)d_in[7];
    const float* gff       = (const float*)d_in[8];
    const float* beff      = (const float*)d_in[9];
    const float* Wq        = (const float*)d_in[10];
    const float* bq        = (const float*)d_in[11];
    const float* Wk        = (const float*)d_in[12];
    const float* bk        = (const float*)d_in[13];
    const float* Wv        = (const float*)d_in[14];
    const float* bv        = (const float*)d_in[15];
    const float* W_ih      = (const float*)d_in[16];
    const float* b_ih      = (const float*)d_in[17];
    const float* W_hh      = (const float*)d_in[18];
    const float* b_hh      = (const float*)d_in[19];
    const float* W1        = (const float*)d_in[20];
    const float* b1        = (const float*)d_in[21];
    const float* W2        = (const float*)d_in[22];
    const float* b2        = (const float*)d_in[23];
    float* slots = (float*)d_out;

    float* xn   = sym(g_xn);
    float* kv   = sym(g_kv);
    float* wkv  = sym(g_wkv);
    float* bkv  = sym(g_bkv);
    float* Wqr  = sym(g_Wq_r);
    float* Wihr = sym(g_Wih_r);
    float* Whhr = sym(g_Whh_r);
    float* W1r  = sym(g_W1_r);
    float* W2r  = sym(g_W2_r);
    float* sbuf = sym(g_s);
    float* srd  = sym(g_sr);
    float* qbuf = sym(g_q);
    float* attn = sym(g_attn);
    float* rsum = sym(g_rowsum);
    float* upd  = sym(g_upd);
    float* xg   = sym(g_xg);
    float* hg   = sym(g_hg);
    float* hid  = sym(g_hid);

    cudaFuncSetAttribute(mma_gemm<0,0,0>, cudaFuncAttributeMaxDynamicSharedMemorySize, GSMEM);
    cudaFuncSetAttribute(mma_gemm<1,0,1>, cudaFuncAttributeMaxDynamicSharedMemorySize, GSMEM);
    cudaFuncSetAttribute(mma_gemm<0,1,0>, cudaFuncAttributeMaxDynamicSharedMemorySize, GSMEM);

    /* weight prep (rounded tf32 copies) */
    pack_kv<<<1024*DIM/256, 256>>>(Wk, bk, Wv, bv, wkv, bkv);
    round_copy<<<DIM*DIM/256, 256>>>(Wq, Wqr, DIM*DIM);
    round_copy<<<3*DIM*DIM/256, 256>>>(W_ih, Wihr, 3*DIM*DIM);
    round_copy<<<3*DIM*DIM/256, 256>>>(W_hh, Whhr, 3*DIM*DIM);
    round_copy<<<HIDN*DIM/256, 256>>>(W1, W1r, HIDN*DIM);
    round_copy<<<DIM*HIDN/256, 256>>>(W2, W2r, DIM*HIDN);

    init_slots<<<SROWS*DIM/256, 256>>>(noise, mu, logsigma, slots);
    ln_rows<<<NROWS, 128>>>(inputs, xn, gi, bei);
    /* fused K|V projection: [131072, 1024] */
    mma_gemm<0,0,0><<<dim3(1024/128, NROWS/128), 256, GSMEM>>>(xn, wkv, bkv, kv, NROWS, 1024, DIM);

    for (int it = 0; it < 3; it++) {
        ln_rows<<<SROWS, 128>>>(slots, sbuf, gsl, besl);
        mma_gemm<0,0,0><<<dim3(DIM/128, SROWS/128), 256, GSMEM>>>(sbuf, Wqr, bq, qbuf, SROWS, DIM, DIM);
        zero_rowsum<<<SROWS/256, 256>>>(rsum);
        dots_softmax<<<dim3(NTOK/128, BATCH), 128>>>(kv, qbuf, attn, rsum);
        attn_apply<<<BATCH, 256>>>(kv, attn, rsum, upd);
        mma_gemm<0,0,0><<<dim3(3*DIM/128, SROWS/128), 256, GSMEM>>>(upd, Wihr, b_ih, xg, SROWS, 3*DIM, DIM);
        round_copy<<<SROWS*DIM/256, 256>>>(slots, srd, SROWS*DIM);
        mma_gemm<0,0,0><<<dim3(3*DIM/128, SROWS/128), 256, GSMEM>>>(srd, Whhr, b_hh, hg, SROWS, 3*DIM, DIM);
        gru_gate<<<SROWS, DIM>>>(xg, hg, slots);
        ln_rows<<<SROWS, 128>>>(slots, sbuf, gff, beff);
        mma_gemm<1,0,1><<<dim3(HIDN/128, SROWS/128), 256, GSMEM>>>(sbuf, W1r, b1, hid, SROWS, HIDN, DIM);
        mma_gemm<0,1,0><<<dim3(DIM/128, SROWS/128), 256, GSMEM>>>(hid, W2r, b2, slots, SROWS, DIM, HIDN);
    }
    (void)in_sizes; (void)n_in; (void)out_size;
}

// round 5
// speedup vs baseline: 2.5471x; 1.1135x over previous
#include <cuda_runtime.h>
#include <math.h>
#include <stdint.h>

#define DIM   512
#define NS    8
#define BATCH 128
#define NTOK  1024
#define HIDN  512
#define NROWS (BATCH*NTOK)   /* 131072 */
#define SROWS (BATCH*NS)     /* 1024   */
#define ATT_SCALE 0.04419417382415922f
#define LN_EPS 1e-5f
#define ATT_EPS 1e-8f

/* ---------------- scratch (device globals; no allocation) ---------------- */
__device__ float g_xn[(size_t)NROWS*DIM];
__device__ float g_kv[(size_t)NROWS*1024];      /* k = cols 0..511, v = cols 512..1023 */
__device__ float g_wkv[1024*DIM];
__device__ float g_bkv[1024];
__device__ float g_Wq_r[DIM*DIM];
__device__ float g_Wih_r[3*DIM*DIM];
__device__ float g_Whh_r[3*DIM*DIM];
__device__ float g_W1_r[HIDN*DIM];
__device__ float g_W2_r[DIM*HIDN];
__device__ float g_s [SROWS*DIM];
__device__ float g_sr[SROWS*DIM];
__device__ float g_q [SROWS*DIM];
__device__ float g_attn[SROWS*NTOK];
__device__ float g_rowsum[SROWS];
__device__ float g_upd[SROWS*DIM];
__device__ float g_xg[SROWS*3*DIM];
__device__ float g_hg[SROWS*3*DIM];
__device__ float g_hid[SROWS*HIDN];

/* ---------------- helpers ---------------- */
__device__ __forceinline__ float rtf32(float x) {
    uint32_t u; asm("cvt.rna.tf32.f32 %0, %1;" : "=r"(u) : "f"(x));
    return __uint_as_float(u);
}
__device__ __forceinline__ uint32_t s2u(const void* p) {
    uint32_t a;
    asm("{ .reg .u64 t; cvta.to.shared.u64 t, %1; cvt.u32.u64 %0, t; }" : "=r"(a) : "l"(p));
    return a;
}

#define CP16(dst, src) \
    asm volatile("cp.async.cg.shared.global [%0], [%1], 16;" :: "r"(dst), "l"(src))
#define CP_COMMIT() asm volatile("cp.async.commit_group;" ::: "memory")
#define CP_WAIT(n)  asm volatile("cp.async.wait_group %0;" :: "n"(n) : "memory")

#define MMA_TF32(d, a, b) \
    asm volatile("mma.sync.aligned.m16n8k8.row.col.f32.tf32.tf32.f32 " \
        "{%0,%1,%2,%3}, {%4,%5,%6,%7}, {%8,%9}, {%0,%1,%2,%3};" \
        : "+f"((d)[0]), "+f"((d)[1]), "+f"((d)[2]), "+f"((d)[3]) \
        : "r"(__float_as_uint((a)[0])), "r"(__float_as_uint((a)[1])), \
          "r"(__float_as_uint((a)[2])), "r"(__float_as_uint((a)[3])), \
          "r"(__float_as_uint((b)[0])), "r"(__float_as_uint((b)[1])))

/* ============ tf32 mma.sync GEMM: C[m,n] = A[m,:]·W[n,:] + bias[n] ============
   BM=BN=128, BK=32, 256 threads (8 warps, 2m x 4n, warp tile 64x32),
   double-buffered cp.async. RC: also store rtf32(result) to Caux. */
#define ASTR 36
#define STG_FLOATS (2 * 128 * ASTR)
#define GSMEM (2 * STG_FLOATS * 4)           /* 73728 bytes */

template<int RELU, int ADDC, int RND, int RC>
__global__ __launch_bounds__(256) void mma_gemm(const float* __restrict__ A,
                                                const float* __restrict__ W,
                                                const float* __restrict__ bias,
                                                float* __restrict__ C,
                                                float* __restrict__ Caux,
                                                int M, int N, int K) {
    extern __shared__ float smem[];
    int tid = threadIdx.x;
    int lane = tid & 31, wid = tid >> 5;
    int wm = wid & 1, wn = wid >> 1;
    int m0 = blockIdx.y * 128, n0 = blockIdx.x * 128;
    int r0 = lane >> 2, k4 = lane & 3;

    float acc[4][4][4];
    #pragma unroll
    for (int mt = 0; mt < 4; mt++)
        #pragma unroll
        for (int nt = 0; nt < 4; nt++)
            #pragma unroll
            for (int i = 0; i < 4; i++) acc[mt][nt][i] = 0.f;

    const int KT = K >> 5;

    auto load_stage = [&](int kt, int s) {
        const float* Ag = A + (size_t)m0 * K + (kt << 5);
        const float* Wg = W + (size_t)n0 * K + (kt << 5);
        float* Ab = smem + s * STG_FLOATS;
        float* Bb = Ab + 128 * ASTR;
        #pragma unroll
        for (int i = 0; i < 4; i++) {
            int idx = tid + (i << 8);
            int r = idx >> 3, c4 = (idx & 7) << 2;
            CP16(s2u(Ab + r * ASTR + c4), Ag + (size_t)r * K + c4);
            CP16(s2u(Bb + r * ASTR + c4), Wg + (size_t)r * K + c4);
        }
    };

    load_stage(0, 0); CP_COMMIT();

    for (int kt = 0; kt < KT; kt++) {
        int s = kt & 1;
        if (kt + 1 < KT) { load_stage(kt + 1, s ^ 1); CP_COMMIT(); CP_WAIT(1); }
        else             { CP_WAIT(0); }
        __syncthreads();

        const float* Ab = smem + s * STG_FLOATS + (wm * 64 + r0) * ASTR + k4;
        const float* Bb = smem + s * STG_FLOATS + 128 * ASTR + (wn * 32 + r0) * ASTR + k4;
        #pragma unroll
        for (int ks = 0; ks < 4; ks++) {
            int kb = ks << 3;
            float af[4][4], bf[4][2];
            #pragma unroll
            for (int mt = 0; mt < 4; mt++) {
                af[mt][0] = Ab[(mt * 16    ) * ASTR + kb];
                af[mt][1] = Ab[(mt * 16 + 8) * ASTR + kb];
                af[mt][2] = Ab[(mt * 16    ) * ASTR + kb + 4];
                af[mt][3] = Ab[(mt * 16 + 8) * ASTR + kb + 4];
            }
            #pragma unroll
            for (int nt = 0; nt < 4; nt++) {
                bf[nt][0] = Bb[nt * 8 * ASTR + kb];
                bf[nt][1] = Bb[nt * 8 * ASTR + kb + 4];
            }
            #pragma unroll
            for (int mt = 0; mt < 4; mt++)
                #pragma unroll
                for (int nt = 0; nt < 4; nt++)
                    MMA_TF32(acc[mt][nt], af[mt], bf[nt]);
        }
        __syncthreads();
    }

    /* epilogue */
    #pragma unroll
    for (int mt = 0; mt < 4; mt++) {
        int mg = m0 + wm * 64 + mt * 16 + r0;
        #pragma unroll
        for (int nt = 0; nt < 4; nt++) {
            int ng = n0 + wn * 32 + nt * 8 + (k4 << 1);
            float b0 = bias[ng], b1 = bias[ng + 1];
            float* c0p = C + (size_t)mg * N + ng;
            float* c1p = C + (size_t)(mg + 8) * N + ng;
            float o0 = acc[mt][nt][0] + b0, o1 = acc[mt][nt][1] + b1;
            float o2 = acc[mt][nt][2] + b0, o3 = acc[mt][nt][3] + b1;
            if (RELU) {
                o0 = fmaxf(o0, 0.f); o1 = fmaxf(o1, 0.f);
                o2 = fmaxf(o2, 0.f); o3 = fmaxf(o3, 0.f);
            }
            if (ADDC) {
                float2 e0 = *(const float2*)c0p;
                float2 e1 = *(const float2*)c1p;
                o0 += e0.x; o1 += e0.y; o2 += e1.x; o3 += e1.y;
            }
            if (RND) { o0 = rtf32(o0); o1 = rtf32(o1); o2 = rtf32(o2); o3 = rtf32(o3); }
            *(float2*)c0p = make_float2(o0, o1);
            *(float2*)c1p = make_float2(o2, o3);
            if (RC) {
                float* a0p = Caux + (size_t)mg * N + ng;
                float* a1p = Caux + (size_t)(mg + 8) * N + ng;
                *(float2*)a0p = make_float2(rtf32(o0), rtf32(o1));
                *(float2*)a1p = make_float2(rtf32(o2), rtf32(o3));
            }
        }
    }
}

/* ---------------- slot init: writes slots and rounded copy ---------------- */
__global__ void init_slots(const float* __restrict__ noise,
                           const float* __restrict__ mu,
                           const float* __restrict__ logsigma,
                           float* __restrict__ slots,
                           float* __restrict__ srd) {
    int idx = blockIdx.x * blockDim.x + threadIdx.x;
    int d = idx & (DIM - 1);
    float v = mu[d] + expf(logsigma[d]) * noise[idx];
    slots[idx] = v;
    srd[idx] = rtf32(v);
}

/* ---------------- pack+round [Wk;Wv] and biases ---------------- */
__global__ void pack_kv(const float* __restrict__ Wk, const float* __restrict__ bk,
                        const float* __restrict__ Wv, const float* __restrict__ bv,
                        float* __restrict__ Wkv, float* __restrict__ bkv) {
    int i = blockIdx.x * 256 + threadIdx.x;
    float w = (i < DIM * DIM) ? Wk[i] : Wv[i - DIM * DIM];
    Wkv[i] = rtf32(w);
    if (i < 1024) bkv[i] = (i < 512) ? bk[i] : bv[i - 512];
}

/* ---------------- round-copy to tf32 (weights only) ---------------- */
__global__ void round_copy(const float* __restrict__ src, float* __restrict__ dst, int n) {
    int i = blockIdx.x * 256 + threadIdx.x;
    if (i < n) dst[i] = rtf32(src[i]);
}

/* ---------------- row LayerNorm (cols = 512), output rounded to tf32 ------- */
__global__ void ln_rows(const float* __restrict__ in, float* __restrict__ out,
                        const float* __restrict__ gamma, const float* __restrict__ beta) {
    int row = blockIdx.x;
    int t = threadIdx.x;
    const float4* ip = (const float4*)(in + (size_t)row * DIM);
    float4 x = ip[t];
    float s  = x.x + x.y + x.z + x.w;
    float ss = x.x*x.x + x.y*x.y + x.z*x.z + x.w*x.w;
    #pragma unroll
    for (int o = 16; o > 0; o >>= 1) {
        s  += __shfl_down_sync(0xffffffffu, s,  o);
        ss += __shfl_down_sync(0xffffffffu, ss, o);
    }
    __shared__ float sh[8];
    int w = t >> 5, l = t & 31;
    if (l == 0) { sh[w] = s; sh[4 + w] = ss; }
    __syncthreads();
    s  = sh[0] + sh[1] + sh[2] + sh[3];
    ss = sh[4] + sh[5] + sh[6] + sh[7];
    float mean = s * (1.0f / DIM);
    float var  = ss * (1.0f / DIM) - mean * mean;
    float rstd = rsqrtf(var + LN_EPS);
    float4 g = ((const float4*)gamma)[t];
    float4 b = ((const float4*)beta)[t];
    float4 o4;
    o4.x = rtf32((x.x - mean) * rstd * g.x + b.x);
    o4.y = rtf32((x.y - mean) * rstd * g.y + b.y);
    o4.z = rtf32((x.z - mean) * rstd * g.z + b.z);
    o4.w = rtf32((x.w - mean) * rstd * g.w + b.w);
    ((float4*)(out + (size_t)row * DIM))[t] = o4;
}

/* ---------------- zero rowsum ---------------- */
__global__ void zero_rowsum(float* __restrict__ rs) {
    rs[blockIdx.x * blockDim.x + threadIdx.x] = 0.f;
}

/* ---- dots + competitive softmax, smem-staged coalesced K reads.
   grid (NTOK/128, BATCH), 128 threads; thread owns token j = j0 + tid.
   kch stride 36 floats = 144 B (16B-aligned rows; LDS.128 conflict-free:
   bank(4t+4c) distinct within each quarter-warp phase). ---- */
#define KSTR 36
__global__ __launch_bounds__(128) void dots_softmax(const float* __restrict__ kv,
                                                    const float* __restrict__ qmat,
                                                    float* __restrict__ attn,
                                                    float* __restrict__ rowsum) {
    int b = blockIdx.y;
    int j0 = blockIdx.x * 128;
    int tid = threadIdx.x;
    __shared__ float qs[NS][DIM];        /* 16 KB */
    __shared__ float kch[128][KSTR];     /* 18 KB */

    {
        const float4* qsrc = (const float4*)(qmat + (size_t)b * NS * DIM);
        for (int idx = tid; idx < NS * DIM / 4; idx += 128) {
            float4 v = qsrc[idx];
            int i = idx >> 7, d4 = idx & 127;
            qs[i][d4*4+0] = v.x; qs[i][d4*4+1] = v.y;
            qs[i][d4*4+2] = v.z; qs[i][d4*4+3] = v.w;
        }
    }

    float acc[NS];
    #pragma unroll
    for (int i = 0; i < NS; i++) acc[i] = 0.f;

    const float* kbase = kv + (size_t)(b * NTOK + j0) * 1024;

    for (int dc = 0; dc < DIM; dc += 32) {
        __syncthreads();
        /* cooperative coalesced load: 128 rows x 32 floats (8 float4/row) */
        #pragma unroll
        for (int ii = 0; ii < 8; ii++) {
            int idx = tid + ii * 128;
            int r = idx >> 3, c4 = idx & 7;
            float4 v = *(const float4*)(kbase + (size_t)r * 1024 + dc + c4 * 4);
            *(float4*)&kch[r][c4 * 4] = v;
        }
        __syncthreads();
        #pragma unroll
        for (int c4 = 0; c4 < 8; c4++) {
            float4 k4 = *(const float4*)&kch[tid][c4 * 4];
            #pragma unroll
            for (int i = 0; i < NS; i++) {
                const float* qp = &qs[i][dc + c4 * 4];
                acc[i] += k4.x*qp[0] + k4.y*qp[1] + k4.z*qp[2] + k4.w*qp[3];
            }
        }
    }

    float m = -1e30f;
    #pragma unroll
    for (int i = 0; i < NS; i++) { acc[i] *= ATT_SCALE; m = fmaxf(m, acc[i]); }
    float sum = 0.f;
    #pragma unroll
    for (int i = 0; i < NS; i++) { acc[i] = expf(acc[i] - m); sum += acc[i]; }
    float inv = 1.0f / sum;
    int j = j0 + tid;
    #pragma unroll
    for (int i = 0; i < NS; i++) {
        float p = acc[i] * inv + ATT_EPS;
        acc[i] = p;
        attn[(size_t)(b * NS + i) * NTOK + j] = p;
    }
    #pragma unroll
    for (int i = 0; i < NS; i++) {
        float s = acc[i];
        #pragma unroll
        for (int o = 16; o > 0; o >>= 1) s += __shfl_down_sync(0xffffffffu, s, o);
        if ((tid & 31) == 0) atomicAdd(&rowsum[b * NS + i], s);
    }
}

/* ---- updates: grid (DIM/128, BATCH), 128 threads, thread owns one d-col ---- */
__global__ __launch_bounds__(128) void attn_apply(const float* __restrict__ kv,
                                                  const float* __restrict__ attn,
                                                  const float* __restrict__ rowsum,
                                                  float* __restrict__ upd) {
    int b = blockIdx.y;
    int d = blockIdx.x * 128 + threadIdx.x;
    int t = threadIdx.x;
    __shared__ float as[NS][256];        /* 8 KB */
    float acc[NS];
    #pragma unroll
    for (int i = 0; i < NS; i++) acc[i] = 0.f;
    const float* vbase = kv + 512 + d;
    for (int j0 = 0; j0 < NTOK; j0 += 256) {
        __syncthreads();
        for (int idx = t; idx < NS * 256; idx += 128) {
            int i = idx >> 8, jj = idx & 255;
            as[i][jj] = attn[(size_t)(b * NS + i) * NTOK + j0 + jj];
        }
        __syncthreads();
        #pragma unroll 8
        for (int jj = 0; jj < 256; jj++) {
            float v = vbase[(size_t)(b * NTOK + j0 + jj) * 1024];
            #pragma unroll
            for (int i = 0; i < NS; i++) acc[i] += v * as[i][jj];
        }
    }
    #pragma unroll
    for (int i = 0; i < NS; i++) {
        float inv = 1.0f / rowsum[b * NS + i];
        upd[(size_t)(b * NS + i) * DIM + d] = rtf32(acc[i] * inv);
    }
}

/* ---------------- GRU gate ---------------- */
__global__ void gru_gate(const float* __restrict__ xg, const float* __restrict__ hg,
                         float* __restrict__ slots) {
    int row = blockIdx.x;
    int c = threadIdx.x;
    size_t base = (size_t)row * 3 * DIM;
    float xr = xg[base + c],         hr = hg[base + c];
    float xz = xg[base + DIM + c],   hz = hg[base + DIM + c];
    float xn = xg[base + 2*DIM + c], hn = hg[base + 2*DIM + c];
    float r = 1.0f / (1.0f + expf(-(xr + hr)));
    float z = 1.0f / (1.0f + expf(-(xz + hz)));
    float n = tanhf(xn + r * hn);
    size_t si = (size_t)row * DIM + c;
    float prev = slots[si];
    slots[si] = (1.0f - z) * n + z * prev;
}

/* ---------------- host ---------------- */
static float* sym(const void* s) {
    void* p = nullptr;
    cudaGetSymbolAddress(&p, s);
    return (float*)p;
}

extern "C" void kernel_launch(void* const* d_in, const int* in_sizes, int n_in,
                              void* d_out, int out_size) {
    const float* inputs    = (const float*)d_in[0];
    const float* noise     = (const float*)d_in[1];
    const float* mu        = (const float*)d_in[2];
    const float* logsigma  = (const float*)d_in[3];
    const float* gi        = (const float*)d_in[4];
    const float* bei       = (const float*)d_in[5];
    const float* gsl       = (const float*)d_in[6];
    const float* besl      = (const float*)d_in[7];
    const float* gff       = (const float*)d_in[8];
    const float* beff      = (const float*)d_in[9];
    const float* Wq        = (const float*)d_in[10];
    const float* bq        = (const float*)d_in[11];
    const float* Wk        = (const float*)d_in[12];
    const float* bk        = (const float*)d_in[13];
    const float* Wv        = (const float*)d_in[14];
    const float* bv        = (const float*)d_in[15];
    const float* W_ih      = (const float*)d_in[16];
    const float* b_ih      = (const float*)d_in[17];
    const float* W_hh      = (const float*)d_in[18];
    const float* b_hh      = (const float*)d_in[19];
    const float* W1        = (const float*)d_in[20];
    const float* b1        = (const float*)d_in[21];
    const float* W2        = (const float*)d_in[22];
    const float* b2        = (const float*)d_in[23];
    float* slots = (float*)d_out;

    float* xn   = sym(g_xn);
    float* kv   = sym(g_kv);
    float* wkv  = sym(g_wkv);
    float* bkv  = sym(g_bkv);
    float* Wqr  = sym(g_Wq_r);
    float* Wihr = sym(g_Wih_r);
    float* Whhr = sym(g_Whh_r);
    float* W1r  = sym(g_W1_r);
    float* W2r  = sym(g_W2_r);
    float* sbuf = sym(g_s);
    float* srd  = sym(g_sr);
    float* qbuf = sym(g_q);
    float* attn = sym(g_attn);
    float* rsum = sym(g_rowsum);
    float* upd  = sym(g_upd);
    float* xg   = sym(g_xg);
    float* hg   = sym(g_hg);
    float* hid  = sym(g_hid);

    cudaFuncSetAttribute(mma_gemm<0,0,0,0>, cudaFuncAttributeMaxDynamicSharedMemorySize, GSMEM);
    cudaFuncSetAttribute(mma_gemm<1,0,1,0>, cudaFuncAttributeMaxDynamicSharedMemorySize, GSMEM);
    cudaFuncSetAttribute(mma_gemm<0,1,0,1>, cudaFuncAttributeMaxDynamicSharedMemorySize, GSMEM);

    /* ordering: KV gemm is the 6th launch so ncu (-s 5 -c 1) captures it */
    init_slots<<<SROWS*DIM/256, 256>>>(noise, mu, logsigma, slots, srd);      /* 1 */
    pack_kv<<<1024*DIM/256, 256>>>(Wk, bk, Wv, bv, wkv, bkv);                 /* 2 */
    ln_rows<<<NROWS, 128>>>(inputs, xn, gi, bei);                             /* 3 */
    round_copy<<<DIM*DIM/256, 256>>>(Wq, Wqr, DIM*DIM);                       /* 4 */
    round_copy<<<3*DIM*DIM/256, 256>>>(W_ih, Wihr, 3*DIM*DIM);                /* 5 */
    mma_gemm<0,0,0,0><<<dim3(1024/128, NROWS/128), 256, GSMEM>>>(             /* 6 */
        xn, wkv, bkv, kv, nullptr, NROWS, 1024, DIM);
    round_copy<<<3*DIM*DIM/256, 256>>>(W_hh, Whhr, 3*DIM*DIM);
    round_copy<<<HIDN*DIM/256, 256>>>(W1, W1r, HIDN*DIM);
    round_copy<<<DIM*HIDN/256, 256>>>(W2, W2r, DIM*HIDN);

    for (int it = 0; it < 3; it++) {
        ln_rows<<<SROWS, 128>>>(slots, sbuf, gsl, besl);
        mma_gemm<0,0,0,0><<<dim3(DIM/128, SROWS/128), 256, GSMEM>>>(sbuf, Wqr, bq, qbuf, nullptr, SROWS, DIM, DIM);
        zero_rowsum<<<SROWS/256, 256>>>(rsum);
        dots_softmax<<<dim3(NTOK/128, BATCH), 128>>>(kv, qbuf, attn, rsum);
        attn_apply<<<dim3(DIM/128, BATCH), 128>>>(kv, attn, rsum, upd);
        mma_gemm<0,0,0,0><<<dim3(3*DIM/128, SROWS/128), 256, GSMEM>>>(upd, Wihr, b_ih, xg, nullptr, SROWS, 3*DIM, DIM);
        mma_gemm<0,0,0,0><<<dim3(3*DIM/128, SROWS/128), 256, GSMEM>>>(srd, Whhr, b_hh, hg, nullptr, SROWS, 3*DIM, DIM);
        gru_gate<<<SROWS, DIM>>>(xg, hg, slots);
        ln_rows<<<SROWS, 128>>>(slots, sbuf, gff, beff);
        mma_gemm<1,0,1,0><<<dim3(HIDN/128, SROWS/128), 256, GSMEM>>>(sbuf, W1r, b1, hid, nullptr, SROWS, HIDN, DIM);
        mma_gemm<0,1,0,1><<<dim3(DIM/128, SROWS/128), 256, GSMEM>>>(hid, W2r, b2, slots, srd, SROWS, DIM, HIDN);
    }
    (void)in_sizes; (void)n_in; (void)out_size;
}

// round 6
// speedup vs baseline: 2.6963x; 1.0585x over previous
#include <cuda_runtime.h>
#include <math.h>
#include <stdint.h>

#define DIM   512
#define NS    8
#define BATCH 128
#define NTOK  1024
#define HIDN  512
#define NROWS (BATCH*NTOK)   /* 131072 */
#define SROWS (BATCH*NS)     /* 1024   */
#define ATT_SCALE 0.04419417382415922f
#define LN_EPS 1e-5f
#define ATT_EPS 1e-8f

/* ---------------- scratch (device globals; no allocation) ---------------- */
__device__ float g_xn[(size_t)NROWS*DIM];
__device__ float g_kv[(size_t)NROWS*1024];      /* k = cols 0..511, v = cols 512..1023 */
__device__ float g_wkv[1024*DIM];
__device__ float g_bkv[1024];
__device__ float g_Wq_r[DIM*DIM];
__device__ float g_Wih_r[3*DIM*DIM];
__device__ float g_Whh_r[3*DIM*DIM];
__device__ float g_W1_r[HIDN*DIM];
__device__ float g_W2_r[DIM*HIDN];
__device__ float g_s [SROWS*DIM];
__device__ float g_sr[SROWS*DIM];
__device__ float g_q [SROWS*DIM];
__device__ float g_attn[SROWS*NTOK];
__device__ float g_upd[SROWS*DIM];
__device__ float g_xg[SROWS*3*DIM];
__device__ float g_hg[SROWS*3*DIM];
__device__ float g_hid[SROWS*HIDN];

/* ---------------- helpers ---------------- */
__device__ __forceinline__ float rtf32(float x) {
    uint32_t u; asm("cvt.rna.tf32.f32 %0, %1;" : "=r"(u) : "f"(x));
    return __uint_as_float(u);
}
__device__ __forceinline__ uint32_t s2u(const void* p) {
    uint32_t a;
    asm("{ .reg .u64 t; cvta.to.shared.u64 t, %1; cvt.u32.u64 %0, t; }" : "=r"(a) : "l"(p));
    return a;
}

#define CP16(dst, src) \
    asm volatile("cp.async.cg.shared.global [%0], [%1], 16;" :: "r"(dst), "l"(src))
#define CP_COMMIT() asm volatile("cp.async.commit_group;" ::: "memory")
#define CP_WAIT(n)  asm volatile("cp.async.wait_group %0;" :: "n"(n) : "memory")

#define MMA_TF32(d, a, b) \
    asm volatile("mma.sync.aligned.m16n8k8.row.col.f32.tf32.tf32.f32 " \
        "{%0,%1,%2,%3}, {%4,%5,%6,%7}, {%8,%9}, {%0,%1,%2,%3};" \
        : "+f"((d)[0]), "+f"((d)[1]), "+f"((d)[2]), "+f"((d)[3]) \
        : "r"(__float_as_uint((a)[0])), "r"(__float_as_uint((a)[1])), \
          "r"(__float_as_uint((a)[2])), "r"(__float_as_uint((a)[3])), \
          "r"(__float_as_uint((b)[0])), "r"(__float_as_uint((b)[1])))

/* ============ tf32 mma.sync GEMM: C[m,n] = A[m,:]·W[n,:] + bias[n] ============
   BM=MT*32, BN=128, BK=32, 256 threads (8 warps, 2m x 4n, warp tile (MT*16)x32),
   double-buffered cp.async. RC: also store rtf32(result) to Caux. */
#define ASTR 36

template<int MT, int RELU, int ADDC, int RND, int RC>
__device__ __forceinline__ void gemm_body(const float* __restrict__ A,
                                          const float* __restrict__ W,
                                          const float* __restrict__ bias,
                                          float* __restrict__ C,
                                          float* __restrict__ Caux,
                                          int M, int N, int K) {
    extern __shared__ float smem[];
    const int BM = MT * 32;
    const int STGF = (BM + 128) * ASTR;
    int tid = threadIdx.x;
    int lane = tid & 31, wid = tid >> 5;
    int wm = wid & 1, wn = wid >> 1;
    int m0 = blockIdx.y * BM, n0 = blockIdx.x * 128;
    int r0 = lane >> 2, k4 = lane & 3;

    float acc[MT][4][4];
    #pragma unroll
    for (int mt = 0; mt < MT; mt++)
        #pragma unroll
        for (int nt = 0; nt < 4; nt++)
            #pragma unroll
            for (int i = 0; i < 4; i++) acc[mt][nt][i] = 0.f;

    const int KT = K >> 5;

    auto load_stage = [&](int kt, int s) {
        const float* Ag = A + (size_t)m0 * K + (kt << 5);
        const float* Wg = W + (size_t)n0 * K + (kt << 5);
        float* Ab = smem + s * STGF;
        float* Bb = Ab + BM * ASTR;
        #pragma unroll
        for (int i = 0; i < MT; i++) {
            int idx = tid + (i << 8);
            int r = idx >> 3, c4 = (idx & 7) << 2;
            CP16(s2u(Ab + r * ASTR + c4), Ag + (size_t)r * K + c4);
        }
        #pragma unroll
        for (int i = 0; i < 4; i++) {
            int idx = tid + (i << 8);
            int r = idx >> 3, c4 = (idx & 7) << 2;
            CP16(s2u(Bb + r * ASTR + c4), Wg + (size_t)r * K + c4);
        }
    };

    load_stage(0, 0); CP_COMMIT();

    for (int kt = 0; kt < KT; kt++) {
        int s = kt & 1;
        if (kt + 1 < KT) { load_stage(kt + 1, s ^ 1); CP_COMMIT(); CP_WAIT(1); }
        else             { CP_WAIT(0); }
        __syncthreads();

        const float* Ab = smem + s * STGF + (wm * (MT * 16) + r0) * ASTR + k4;
        const float* Bb = smem + s * STGF + BM * ASTR + (wn * 32 + r0) * ASTR + k4;
        #pragma unroll
        for (int ks = 0; ks < 4; ks++) {
            int kb = ks << 3;
            float af[MT][4], bf[4][2];
            #pragma unroll
            for (int mt = 0; mt < MT; mt++) {
                af[mt][0] = Ab[(mt * 16    ) * ASTR + kb];
                af[mt][1] = Ab[(mt * 16 + 8) * ASTR + kb];
                af[mt][2] = Ab[(mt * 16    ) * ASTR + kb + 4];
                af[mt][3] = Ab[(mt * 16 + 8) * ASTR + kb + 4];
            }
            #pragma unroll
            for (int nt = 0; nt < 4; nt++) {
                bf[nt][0] = Bb[nt * 8 * ASTR + kb];
                bf[nt][1] = Bb[nt * 8 * ASTR + kb + 4];
            }
            #pragma unroll
            for (int mt = 0; mt < MT; mt++)
                #pragma unroll
                for (int nt = 0; nt < 4; nt++)
                    MMA_TF32(acc[mt][nt], af[mt], bf[nt]);
        }
        __syncthreads();
    }

    /* epilogue */
    #pragma unroll
    for (int mt = 0; mt < MT; mt++) {
        int mg = m0 + wm * (MT * 16) + mt * 16 + r0;
        #pragma unroll
        for (int nt = 0; nt < 4; nt++) {
            int ng = n0 + wn * 32 + nt * 8 + (k4 << 1);
            float b0 = bias[ng], b1 = bias[ng + 1];
            float* c0p = C + (size_t)mg * N + ng;
            float* c1p = C + (size_t)(mg + 8) * N + ng;
            float o0 = acc[mt][nt][0] + b0, o1 = acc[mt][nt][1] + b1;
            float o2 = acc[mt][nt][2] + b0, o3 = acc[mt][nt][3] + b1;
            if (RELU) {
                o0 = fmaxf(o0, 0.f); o1 = fmaxf(o1, 0.f);
                o2 = fmaxf(o2, 0.f); o3 = fmaxf(o3, 0.f);
            }
            if (ADDC) {
                float2 e0 = *(const float2*)c0p;
                float2 e1 = *(const float2*)c1p;
                o0 += e0.x; o1 += e0.y; o2 += e1.x; o3 += e1.y;
            }
            if (RND) { o0 = rtf32(o0); o1 = rtf32(o1); o2 = rtf32(o2); o3 = rtf32(o3); }
            *(float2*)c0p = make_float2(o0, o1);
            *(float2*)c1p = make_float2(o2, o3);
            if (RC) {
                float* a0p = Caux + (size_t)mg * N + ng;
                float* a1p = Caux + (size_t)(mg + 8) * N + ng;
                *(float2*)a0p = make_float2(rtf32(o0), rtf32(o1));
                *(float2*)a1p = make_float2(rtf32(o2), rtf32(o3));
            }
        }
    }
}

template<int MT, int RELU, int ADDC, int RND, int RC>
__global__ __launch_bounds__(256) void mma_gemm(const float* __restrict__ A,
                                                const float* __restrict__ W,
                                                const float* __restrict__ bias,
                                                float* __restrict__ C,
                                                float* __restrict__ Caux,
                                                int M, int N, int K) {
    gemm_body<MT, RELU, ADDC, RND, RC>(A, W, bias, C, Caux, M, N, K);
}

/* dual GEMM: blockIdx.z selects operand set (same shape). */
template<int MT>
__global__ __launch_bounds__(256) void mma_gemm_dual(const float* __restrict__ A0,
                                                     const float* __restrict__ W0,
                                                     const float* __restrict__ b0,
                                                     float* __restrict__ C0,
                                                     const float* __restrict__ A1,
                                                     const float* __restrict__ W1,
                                                     const float* __restrict__ b1,
                                                     float* __restrict__ C1,
                                                     int M, int N, int K) {
    if (blockIdx.z == 0) gemm_body<MT, 0, 0, 0, 0>(A0, W0, b0, C0, nullptr, M, N, K);
    else                 gemm_body<MT, 0, 0, 0, 0>(A1, W1, b1, C1, nullptr, M, N, K);
}

#define GSMEM128 ((128 + 128) * ASTR * 4 * 2)   /* 73728 */
#define GSMEM64  ((64 + 128) * ASTR * 4 * 2)    /* 55296 */

/* ---------------- slot init: writes slots and rounded copy ---------------- */
__global__ void init_slots(const float* __restrict__ noise,
                           const float* __restrict__ mu,
                           const float* __restrict__ logsigma,
                           float* __restrict__ slots,
                           float* __restrict__ srd) {
    int idx = blockIdx.x * blockDim.x + threadIdx.x;
    int d = idx & (DIM - 1);
    float v = mu[d] + expf(logsigma[d]) * noise[idx];
    slots[idx] = v;
    srd[idx] = rtf32(v);
}

/* ---------------- pack+round [Wk;Wv] and biases ---------------- */
__global__ void pack_kv(const float* __restrict__ Wk, const float* __restrict__ bk,
                        const float* __restrict__ Wv, const float* __restrict__ bv,
                        float* __restrict__ Wkv, float* __restrict__ bkv) {
    int i = blockIdx.x * 256 + threadIdx.x;
    float w = (i < DIM * DIM) ? Wk[i] : Wv[i - DIM * DIM];
    Wkv[i] = rtf32(w);
    if (i < 1024) bkv[i] = (i < 512) ? bk[i] : bv[i - 512];
}

/* ---------------- round-copy to tf32 (weights only) ---------------- */
__global__ void round_copy(const float* __restrict__ src, float* __restrict__ dst, int n) {
    int i = blockIdx.x * 256 + threadIdx.x;
    if (i < n) dst[i] = rtf32(src[i]);
}

/* ---------------- row LayerNorm (cols = 512), output rounded to tf32 ------- */
__global__ void ln_rows(const float* __restrict__ in, float* __restrict__ out,
                        const float* __restrict__ gamma, const float* __restrict__ beta) {
    int row = blockIdx.x;
    int t = threadIdx.x;
    const float4* ip = (const float4*)(in + (size_t)row * DIM);
    float4 x = ip[t];
    float s  = x.x + x.y + x.z + x.w;
    float ss = x.x*x.x + x.y*x.y + x.z*x.z + x.w*x.w;
    #pragma unroll
    for (int o = 16; o > 0; o >>= 1) {
        s  += __shfl_down_sync(0xffffffffu, s,  o);
        ss += __shfl_down_sync(0xffffffffu, ss, o);
    }
    __shared__ float sh[8];
    int w = t >> 5, l = t & 31;
    if (l == 0) { sh[w] = s; sh[4 + w] = ss; }
    __syncthreads();
    s  = sh[0] + sh[1] + sh[2] + sh[3];
    ss = sh[4] + sh[5] + sh[6] + sh[7];
    float mean = s * (1.0f / DIM);
    float var  = ss * (1.0f / DIM) - mean * mean;
    float rstd = rsqrtf(var + LN_EPS);
    float4 g = ((const float4*)gamma)[t];
    float4 b = ((const float4*)beta)[t];
    float4 o4;
    o4.x = rtf32((x.x - mean) * rstd * g.x + b.x);
    o4.y = rtf32((x.y - mean) * rstd * g.y + b.y);
    o4.z = rtf32((x.z - mean) * rstd * g.z + b.z);
    o4.w = rtf32((x.w - mean) * rstd * g.w + b.w);
    ((float4*)(out + (size_t)row * DIM))[t] = o4;
}

/* ---- dots + competitive softmax, smem-staged coalesced K reads.
   grid (NTOK/128, BATCH), 128 threads; thread owns token j = j0 + tid.
   kch stride 36 floats = 144 B (16B-aligned rows, conflict-free). ---- */
#define KSTR 36
__global__ __launch_bounds__(128) void dots_softmax(const float* __restrict__ kv,
                                                    const float* __restrict__ qmat,
                                                    float* __restrict__ attn) {
    int b = blockIdx.y;
    int j0 = blockIdx.x * 128;
    int tid = threadIdx.x;
    __shared__ float qs[NS][DIM];        /* 16 KB */
    __shared__ float kch[128][KSTR];     /* 18 KB */

    {
        const float4* qsrc = (const float4*)(qmat + (size_t)b * NS * DIM);
        for (int idx = tid; idx < NS * DIM / 4; idx += 128) {
            float4 v = qsrc[idx];
            int i = idx >> 7, d4 = idx & 127;
            qs[i][d4*4+0] = v.x; qs[i][d4*4+1] = v.y;
            qs[i][d4*4+2] = v.z; qs[i][d4*4+3] = v.w;
        }
    }

    float acc[NS];
    #pragma unroll
    for (int i = 0; i < NS; i++) acc[i] = 0.f;

    const float* kbase = kv + (size_t)(b * NTOK + j0) * 1024;

    for (int dc = 0; dc < DIM; dc += 32) {
        __syncthreads();
        #pragma unroll
        for (int ii = 0; ii < 8; ii++) {
            int idx = tid + ii * 128;
            int r = idx >> 3, c4 = idx & 7;
            float4 v = *(const float4*)(kbase + (size_t)r * 1024 + dc + c4 * 4);
            *(float4*)&kch[r][c4 * 4] = v;
        }
        __syncthreads();
        #pragma unroll
        for (int c4 = 0; c4 < 8; c4++) {
            float4 k4 = *(const float4*)&kch[tid][c4 * 4];
            #pragma unroll
            for (int i = 0; i < NS; i++) {
                const float* qp = &qs[i][dc + c4 * 4];
                acc[i] += k4.x*qp[0] + k4.y*qp[1] + k4.z*qp[2] + k4.w*qp[3];
            }
        }
    }

    float m = -1e30f;
    #pragma unroll
    for (int i = 0; i < NS; i++) { acc[i] *= ATT_SCALE; m = fmaxf(m, acc[i]); }
    float sum = 0.f;
    #pragma unroll
    for (int i = 0; i < NS; i++) { acc[i] = expf(acc[i] - m); sum += acc[i]; }
    float inv = 1.0f / sum;
    int j = j0 + tid;
    #pragma unroll
    for (int i = 0; i < NS; i++)
        attn[(size_t)(b * NS + i) * NTOK + j] = acc[i] * inv + ATT_EPS;
}

/* ---- updates: grid (DIM/128, BATCH), 128 threads, thread owns one d-col.
   rowsum computed in-block from the staged attn values. ---- */
__global__ __launch_bounds__(128) void attn_apply(const float* __restrict__ kv,
                                                  const float* __restrict__ attn,
                                                  float* __restrict__ upd) {
    int b = blockIdx.y;
    int d = blockIdx.x * 128 + threadIdx.x;
    int t = threadIdx.x;
    __shared__ float as[NS][256];        /* 8 KB */
    __shared__ float rs[NS][4];
    float acc[NS], psum[NS];
    #pragma unroll
    for (int i = 0; i < NS; i++) { acc[i] = 0.f; psum[i] = 0.f; }
    const float* vbase = kv + 512 + d;
    for (int j0 = 0; j0 < NTOK; j0 += 256) {
        __syncthreads();
        /* idx = t + 128*s: slot index i = s>>1 (compile-time per unrolled s) */
        #pragma unroll
        for (int s = 0; s < 16; s++) {
            int i = s >> 1;
            int jj = (t + (s << 7)) & 255;
            float a = attn[(size_t)(b * NS + i) * NTOK + j0 + jj];
            as[i][jj] = a;
            psum[i] += a;
        }
        __syncthreads();
        #pragma unroll 8
        for (int jj = 0; jj < 256; jj++) {
            float v = vbase[(size_t)(b * NTOK + j0 + jj) * 1024];
            #pragma unroll
            for (int i = 0; i < NS; i++) acc[i] += v * as[i][jj];
        }
    }
    /* block-reduce psum -> rowsum */
    int w = t >> 5, l = t & 31;
    #pragma unroll
    for (int i = 0; i < NS; i++) {
        float s = psum[i];
        #pragma unroll
        for (int o = 16; o > 0; o >>= 1) s += __shfl_down_sync(0xffffffffu, s, o);
        if (l == 0) rs[i][w] = s;
    }
    __syncthreads();
    #pragma unroll
    for (int i = 0; i < NS; i++) {
        float rowsum = rs[i][0] + rs[i][1] + rs[i][2] + rs[i][3];
        upd[(size_t)(b * NS + i) * DIM + d] = rtf32(acc[i] / rowsum);
    }
}

/* ---------------- GRU gate ---------------- */
__global__ void gru_gate(const float* __restrict__ xg, const float* __restrict__ hg,
                         float* __restrict__ slots) {
    int row = blockIdx.x;
    int c = threadIdx.x;
    size_t base = (size_t)row * 3 * DIM;
    float xr = xg[base + c],         hr = hg[base + c];
    float xz = xg[base + DIM + c],   hz = hg[base + DIM + c];
    float xn = xg[base + 2*DIM + c], hn = hg[base + 2*DIM + c];
    float r = 1.0f / (1.0f + expf(-(xr + hr)));
    float z = 1.0f / (1.0f + expf(-(xz + hz)));
    float n = tanhf(xn + r * hn);
    size_t si = (size_t)row * DIM + c;
    float prev = slots[si];
    slots[si] = (1.0f - z) * n + z * prev;
}

/* ---------------- host ---------------- */
static float* sym(const void* s) {
    void* p = nullptr;
    cudaGetSymbolAddress(&p, s);
    return (float*)p;
}

extern "C" void kernel_launch(void* const* d_in, const int* in_sizes, int n_in,
                              void* d_out, int out_size) {
    const float* inputs    = (const float*)d_in[0];
    const float* noise     = (const float*)d_in[1];
    const float* mu        = (const float*)d_in[2];
    const float* logsigma  = (const float*)d_in[3];
    const float* gi        = (const float*)d_in[4];
    const float* bei       = (const float*)d_in[5];
    const float* gsl       = (const float*)d_in[6];
    const float* besl      = (const float*)d_in[7];
    const float* gff       = (const float*)d_in[8];
    const float* beff      = (const float*)d_in[9];
    const float* Wq        = (const float*)d_in[10];
    const float* bq        = (const float*)d_in[11];
    const float* Wk        = (const float*)d_in[12];
    const float* bk        = (const float*)d_in[13];
    const float* Wv        = (const float*)d_in[14];
    const float* bv        = (const float*)d_in[15];
    const float* W_ih      = (const float*)d_in[16];
    const float* b_ih      = (const float*)d_in[17];
    const float* W_hh      = (const float*)d_in[18];
    const float* b_hh      = (const float*)d_in[19];
    const float* W1        = (const float*)d_in[20];
    const float* b1        = (const float*)d_in[21];
    const float* W2        = (const float*)d_in[22];
    const float* b2        = (const float*)d_in[23];
    float* slots = (float*)d_out;

    float* xn   = sym(g_xn);
    float* kv   = sym(g_kv);
    float* wkv  = sym(g_wkv);
    float* bkv  = sym(g_bkv);
    float* Wqr  = sym(g_Wq_r);
    float* Wihr = sym(g_Wih_r);
    float* Whhr = sym(g_Whh_r);
    float* W1r  = sym(g_W1_r);
    float* W2r  = sym(g_W2_r);
    float* sbuf = sym(g_s);
    float* srd  = sym(g_sr);
    float* qbuf = sym(g_q);
    float* attn = sym(g_attn);
    float* upd  = sym(g_upd);
    float* xg   = sym(g_xg);
    float* hg   = sym(g_hg);
    float* hid  = sym(g_hid);

    cudaFuncSetAttribute(mma_gemm<4,0,0,0,0>, cudaFuncAttributeMaxDynamicSharedMemorySize, GSMEM128);
    cudaFuncSetAttribute(mma_gemm<2,0,0,0,0>, cudaFuncAttributeMaxDynamicSharedMemorySize, GSMEM64);
    cudaFuncSetAttribute(mma_gemm<2,1,0,1,0>, cudaFuncAttributeMaxDynamicSharedMemorySize, GSMEM64);
    cudaFuncSetAttribute(mma_gemm<2,0,1,0,1>, cudaFuncAttributeMaxDynamicSharedMemorySize, GSMEM64);
    cudaFuncSetAttribute(mma_gemm_dual<2>,    cudaFuncAttributeMaxDynamicSharedMemorySize, GSMEM64);

    /* KV gemm is my launch #4 (harness prepends ~2 launches; ncu -s 5 -> #4 here) */
    init_slots<<<SROWS*DIM/256, 256>>>(noise, mu, logsigma, slots, srd);      /* 1 */
    pack_kv<<<1024*DIM/256, 256>>>(Wk, bk, Wv, bv, wkv, bkv);                 /* 2 */
    ln_rows<<<NROWS, 128>>>(inputs, xn, gi, bei);                             /* 3 */
    mma_gemm<4,0,0,0,0><<<dim3(1024/128, NROWS/128), 256, GSMEM128>>>(        /* 4 */
        xn, wkv, bkv, kv, nullptr, NROWS, 1024, DIM);
    round_copy<<<DIM*DIM/256, 256>>>(Wq, Wqr, DIM*DIM);
    round_copy<<<3*DIM*DIM/256, 256>>>(W_ih, Wihr, 3*DIM*DIM);
    round_copy<<<3*DIM*DIM/256, 256>>>(W_hh, Whhr, 3*DIM*DIM);
    round_copy<<<HIDN*DIM/256, 256>>>(W1, W1r, HIDN*DIM);
    round_copy<<<DIM*HIDN/256, 256>>>(W2, W2r, DIM*HIDN);

    for (int it = 0; it < 3; it++) {
        ln_rows<<<SROWS, 128>>>(slots, sbuf, gsl, besl);
        mma_gemm<2,0,0,0,0><<<dim3(DIM/128, SROWS/64), 256, GSMEM64>>>(sbuf, Wqr, bq, qbuf, nullptr, SROWS, DIM, DIM);
        dots_softmax<<<dim3(NTOK/128, BATCH), 128>>>(kv, qbuf, attn);
        attn_apply<<<dim3(DIM/128, BATCH), 128>>>(kv, attn, upd);
        mma_gemm_dual<2><<<dim3(3*DIM/128, SROWS/64, 2), 256, GSMEM64>>>(
            upd, Wihr, b_ih, xg, srd, Whhr, b_hh, hg, SROWS, 3*DIM, DIM);
        gru_gate<<<SROWS, DIM>>>(xg, hg, slots);
        ln_rows<<<SROWS, 128>>>(slots, sbuf, gff, beff);
        mma_gemm<2,1,0,1,0><<<dim3(HIDN/128, SROWS/64), 256, GSMEM64>>>(sbuf, W1r, b1, hid, nullptr, SROWS, HIDN, DIM);
        mma_gemm<2,0,1,0,1><<<dim3(DIM/128, SROWS/64), 256, GSMEM64>>>(hid, W2r, b2, slots, srd, SROWS, DIM, HIDN);
    }
    (void)in_sizes; (void)n_in; (void)out_size;
}